// round 1
// baseline (speedup 1.0000x reference)
#include <cuda_runtime.h>
#include <cuda_bf16.h>
#include <cstdint>
#include <math.h>

// Problem constants (fixed by the dataset)
#define N0 30000
#define N1 50000
#define N2 20000
#define NTOT 100000
#define NE 1600000
#define NR 6
#define RN (NR * NTOT)

// ---------------------------------------------------------------------------
// Scratch (static __device__ globals; allocation-free per harness rules)
// ---------------------------------------------------------------------------
__device__ float g_x[(size_t)NTOT * 128];     // concat of projected inputs   51.2 MB
__device__ float g_xt1[(size_t)NTOT * 384];   // layer1 per-relation transform 153.6 MB
__device__ float g_agg1[(size_t)NTOT * 64];   // layer1 accumulator / h1       25.6 MB
__device__ float g_xt2[(size_t)NTOT * 96];    // layer2 per-relation transform 38.4 MB
__device__ float g_agg2[(size_t)NTOT * 16];   // layer2 accumulator / h2        6.4 MB
__device__ int   g_cnt[RN];                   // per (r,dst) edge counts
__device__ float g_inv[RN];                   // 1 / max(cnt,1)
__device__ float g_W1[448 * 128];             // [n][k]: 6*64 relation cols + 64 root cols
__device__ float g_W2[112 * 64];              // [n][k]: 6*16 relation cols + 16 root cols

// ---------------------------------------------------------------------------
// Small helper kernels
// ---------------------------------------------------------------------------
__global__ void zero_cnt_kernel() {
    int i = blockIdx.x * blockDim.x + threadIdx.x;
    if (i < RN) g_cnt[i] = 0;
}

__global__ void count_kernel(const int* __restrict__ dst, const int* __restrict__ et) {
    int e = blockIdx.x * blockDim.x + threadIdx.x;
    if (e < NE) atomicAdd(&g_cnt[et[e] * NTOT + dst[e]], 1);
}

__global__ void inv_kernel() {
    int i = blockIdx.x * blockDim.x + threadIdx.x;
    if (i < RN) {
        int c = g_cnt[i];
        g_inv[i] = 1.0f / (float)(c > 1 ? c : 1);
    }
}

// W1[n][k]: n<384 -> r=n/64,o=n%64: sum_b comp1[r,b]*bases1[b,k,o]; n>=384 -> root1[k, n-384]
__global__ void build_w1(const float* __restrict__ comp1, const float* __restrict__ bases1,
                         const float* __restrict__ root1) {
    int idx = blockIdx.x * blockDim.x + threadIdx.x;
    if (idx >= 448 * 128) return;
    int n = idx >> 7, k = idx & 127;
    float v;
    if (n < 384) {
        int r = n >> 6, o = n & 63;
        v = 0.0f;
        #pragma unroll
        for (int b = 0; b < 30; b++)
            v += comp1[r * 30 + b] * bases1[((size_t)b * 128 + k) * 64 + o];
    } else {
        v = root1[k * 64 + (n - 384)];
    }
    g_W1[idx] = v;
}

// W2[n][k]: n<96 -> r=n/16,o=n%16: sum_b comp2[r,b]*bases2[b,k,o]; n>=96 -> root2[k, n-96]
__global__ void build_w2(const float* __restrict__ comp2, const float* __restrict__ bases2,
                         const float* __restrict__ root2) {
    int idx = blockIdx.x * blockDim.x + threadIdx.x;
    if (idx >= 112 * 64) return;
    int n = idx >> 6, k = idx & 63;
    float v;
    if (n < 96) {
        int r = n >> 4, o = n & 15;
        v = 0.0f;
        #pragma unroll
        for (int b = 0; b < 30; b++)
            v += comp2[r * 30 + b] * bases2[((size_t)b * 64 + k) * 16 + o];
    } else {
        v = root2[k * 16 + (n - 96)];
    }
    g_W2[idx] = v;
}

// ---------------------------------------------------------------------------
// SGEMM: C[m,n] = sum_k A[m,k] * Bw[n,k] (+bias), split output regions.
//   cols [0, n1)      -> C1[m*n1 + n]          (+ b1[n]      if b1)
//   cols [n1, N)      -> C2[m*(N-n1) + (n-n1)] (+ b2[n-n1]   if b2)
// BM=BN=128, BK=8, 256 threads, 8x8 per thread. K must be a multiple of 8.
// ---------------------------------------------------------------------------
#define BM 128
#define BN 128
#define BK 8

__global__ __launch_bounds__(256)
void sgemm_split(const float* __restrict__ A, const float* __restrict__ Bw,
                 int M, int N, int K,
                 float* __restrict__ C1, int n1, const float* __restrict__ b1,
                 float* __restrict__ C2, const float* __restrict__ b2) {
    __shared__ float As[BK][BM];
    __shared__ float Bs[BK][BN];

    const int bm = blockIdx.y * BM;
    const int bn = blockIdx.x * BN;
    const int tid = threadIdx.x;
    const int tm = tid >> 4;        // 0..15
    const int tn = tid & 15;        // 0..15
    const int lr = tid >> 1;        // 0..127
    const int lk = (tid & 1) * 4;   // 0 or 4

    float acc[8][8] = {};

    for (int k0 = 0; k0 < K; k0 += BK) {
        float4 av = make_float4(0.f, 0.f, 0.f, 0.f);
        if (bm + lr < M)
            av = *(const float4*)(A + (size_t)(bm + lr) * K + k0 + lk);
        As[lk + 0][lr] = av.x; As[lk + 1][lr] = av.y;
        As[lk + 2][lr] = av.z; As[lk + 3][lr] = av.w;

        float4 bv = make_float4(0.f, 0.f, 0.f, 0.f);
        if (bn + lr < N)
            bv = *(const float4*)(Bw + (size_t)(bn + lr) * K + k0 + lk);
        Bs[lk + 0][lr] = bv.x; Bs[lk + 1][lr] = bv.y;
        Bs[lk + 2][lr] = bv.z; Bs[lk + 3][lr] = bv.w;

        __syncthreads();

        #pragma unroll
        for (int k = 0; k < BK; k++) {
            float4 a0 = *(const float4*)&As[k][tm * 8];
            float4 a1 = *(const float4*)&As[k][tm * 8 + 4];
            float4 b0 = *(const float4*)&Bs[k][tn * 8];
            float4 b1v = *(const float4*)&Bs[k][tn * 8 + 4];
            float ar[8] = {a0.x, a0.y, a0.z, a0.w, a1.x, a1.y, a1.z, a1.w};
            float br[8] = {b0.x, b0.y, b0.z, b0.w, b1v.x, b1v.y, b1v.z, b1v.w};
            #pragma unroll
            for (int i = 0; i < 8; i++)
                #pragma unroll
                for (int j = 0; j < 8; j++)
                    acc[i][j] += ar[i] * br[j];
        }
        __syncthreads();
    }

    const int n2w = N - n1;
    #pragma unroll
    for (int i = 0; i < 8; i++) {
        int m = bm + tm * 8 + i;
        if (m >= M) continue;
        #pragma unroll
        for (int j = 0; j < 8; j++) {
            int n = bn + tn * 8 + j;
            if (n >= N) continue;
            float v = acc[i][j];
            if (n < n1) {
                C1[(size_t)m * n1 + n] = v + (b1 ? b1[n] : 0.0f);
            } else {
                C2[(size_t)m * n2w + (n - n1)] = v + (b2 ? b2[n - n1] : 0.0f);
            }
        }
    }
}

// ---------------------------------------------------------------------------
// Edge scatter kernels: agg[dst] += inv[type,dst] * xt[src, type*dout .. ]
// ---------------------------------------------------------------------------
__device__ __forceinline__ void red_add_v4(float* addr, float4 v) {
    asm volatile("red.global.add.v4.f32 [%0], {%1, %2, %3, %4};"
                 :: "l"(addr), "f"(v.x), "f"(v.y), "f"(v.z), "f"(v.w)
                 : "memory");
}

// Layer 1: dout=64, 16 threads per edge (each thread does one float4)
__global__ __launch_bounds__(256)
void edge_scatter_64(const int* __restrict__ ei, const int* __restrict__ et) {
    int t = blockIdx.x * blockDim.x + threadIdx.x;
    int e = t >> 4;
    if (e >= NE) return;
    int lane = t & 15;
    int s = ei[e];
    int d = ei[NE + e];
    int r = et[e];
    float w = g_inv[r * NTOT + d];
    float4 v = *(const float4*)(g_xt1 + (size_t)s * 384 + r * 64 + lane * 4);
    red_add_v4(g_agg1 + (size_t)d * 64 + lane * 4,
               make_float4(v.x * w, v.y * w, v.z * w, v.w * w));
}

// Layer 2: dout=16, 4 threads per edge
__global__ __launch_bounds__(256)
void edge_scatter_16(const int* __restrict__ ei, const int* __restrict__ et) {
    int t = blockIdx.x * blockDim.x + threadIdx.x;
    int e = t >> 2;
    if (e >= NE) return;
    int lane = t & 3;
    int s = ei[e];
    int d = ei[NE + e];
    int r = et[e];
    float w = g_inv[r * NTOT + d];
    float4 v = *(const float4*)(g_xt2 + (size_t)s * 96 + r * 16 + lane * 4);
    red_add_v4(g_agg2 + (size_t)d * 16 + lane * 4,
               make_float4(v.x * w, v.y * w, v.z * w, v.w * w));
}

// ---------------------------------------------------------------------------
// Softmax over the first N0 rows (16 cols each)
// ---------------------------------------------------------------------------
__global__ void softmax_kernel(float* __restrict__ out) {
    int row = blockIdx.x * blockDim.x + threadIdx.x;
    if (row >= N0) return;
    const float* p = g_agg2 + (size_t)row * 16;
    float v[16];
    #pragma unroll
    for (int i = 0; i < 4; i++) {
        float4 q = *(const float4*)(p + i * 4);
        v[i * 4 + 0] = q.x; v[i * 4 + 1] = q.y; v[i * 4 + 2] = q.z; v[i * 4 + 3] = q.w;
    }
    float mx = v[0];
    #pragma unroll
    for (int i = 1; i < 16; i++) mx = fmaxf(mx, v[i]);
    float s = 0.0f;
    #pragma unroll
    for (int i = 0; i < 16; i++) { v[i] = expf(v[i] - mx); s += v[i]; }
    float inv = 1.0f / s;
    float* o = out + (size_t)row * 16;
    #pragma unroll
    for (int i = 0; i < 4; i++) {
        float4 q = make_float4(v[i * 4 + 0] * inv, v[i * 4 + 1] * inv,
                               v[i * 4 + 2] * inv, v[i * 4 + 3] * inv);
        *(float4*)(o + i * 4) = q;
    }
}

// ---------------------------------------------------------------------------
// Launcher
// ---------------------------------------------------------------------------
extern "C" void kernel_launch(void* const* d_in, const int* in_sizes, int n_in,
                              void* d_out, int out_size) {
    (void)in_sizes; (void)n_in; (void)out_size;
    const float* x0     = (const float*)d_in[0];
    const float* x1     = (const float*)d_in[1];
    const float* x2     = (const float*)d_in[2];
    const float* lin_w0 = (const float*)d_in[3];
    const float* lin_b0 = (const float*)d_in[4];
    const float* lin_w1 = (const float*)d_in[5];
    const float* lin_b1 = (const float*)d_in[6];
    const float* lin_w2 = (const float*)d_in[7];
    const float* lin_b2 = (const float*)d_in[8];
    const float* bases1 = (const float*)d_in[9];
    const float* comp1  = (const float*)d_in[10];
    const float* root1  = (const float*)d_in[11];
    const float* bias1  = (const float*)d_in[12];
    const float* bases2 = (const float*)d_in[13];
    const float* comp2  = (const float*)d_in[14];
    const float* root2  = (const float*)d_in[15];
    const float* bias2  = (const float*)d_in[16];
    const int*   eidx   = (const int*)d_in[17];
    const int*   etyp   = (const int*)d_in[18];
    float* out = (float*)d_out;

    float *xb, *xt1, *agg1, *xt2, *agg2, *W1, *W2;
    cudaGetSymbolAddress((void**)&xb,   g_x);
    cudaGetSymbolAddress((void**)&xt1,  g_xt1);
    cudaGetSymbolAddress((void**)&agg1, g_agg1);
    cudaGetSymbolAddress((void**)&xt2,  g_xt2);
    cudaGetSymbolAddress((void**)&agg2, g_agg2);
    cudaGetSymbolAddress((void**)&W1,   g_W1);
    cudaGetSymbolAddress((void**)&W2,   g_W2);

    // counts (shared by both layers)
    zero_cnt_kernel<<<(RN + 255) / 256, 256>>>();
    count_kernel<<<(NE + 255) / 256, 256>>>(eidx + NE, etyp);
    inv_kernel<<<(RN + 255) / 256, 256>>>();

    // typed input projections -> g_x
    sgemm_split<<<dim3(1, (N0 + BM - 1) / BM), 256>>>(
        x0, lin_w0, N0, 128, 256, xb, 128, lin_b0, nullptr, nullptr);
    sgemm_split<<<dim3(1, (N1 + BM - 1) / BM), 256>>>(
        x1, lin_w1, N1, 128, 512, xb + (size_t)N0 * 128, 128, lin_b1, nullptr, nullptr);
    sgemm_split<<<dim3(1, (N2 + BM - 1) / BM), 256>>>(
        x2, lin_w2, N2, 128, 128, xb + (size_t)(N0 + N1) * 128, 128, lin_b2, nullptr, nullptr);

    // layer 1: xt1 (relation cols) + agg1 init (root+bias cols)
    build_w1<<<(448 * 128 + 255) / 256, 256>>>(comp1, bases1, root1);
    sgemm_split<<<dim3(4, (NTOT + BM - 1) / BM), 256>>>(
        xb, W1, NTOT, 448, 128, xt1, 384, nullptr, agg1, bias1);
    edge_scatter_64<<<(NE * 16) / 256, 256>>>(eidx, etyp);

    // layer 2: xt2 + agg2 init
    build_w2<<<(112 * 64 + 255) / 256, 256>>>(comp2, bases2, root2);
    sgemm_split<<<dim3(1, (NTOT + BM - 1) / BM), 256>>>(
        agg1, W2, NTOT, 112, 64, xt2, 96, nullptr, agg2, bias2);
    edge_scatter_16<<<(NE * 4) / 256, 256>>>(eidx, etyp);

    // softmax over author rows
    softmax_kernel<<<(N0 + 255) / 256, 256>>>(out);
}

// round 3
// speedup vs baseline: 2.2276x; 2.2276x over previous
#include <cuda_runtime.h>
#include <cuda_bf16.h>
#include <cstdint>
#include <math.h>

// Problem constants (fixed by the dataset)
#define N0 30000
#define N1 50000
#define N2 20000
#define NTOT 100000
#define NE 1600000
#define NR 6
#define RN (NR * NTOT)

// ---------------------------------------------------------------------------
// Scratch (static __device__ globals; allocation-free per harness rules)
// ---------------------------------------------------------------------------
__device__ float g_x[(size_t)NTOT * 128];     // concat of projected inputs
__device__ float g_xt1[(size_t)NTOT * 384];   // layer1 per-relation transform
__device__ float g_agg1[(size_t)NTOT * 64];   // layer1 accumulator / h1
__device__ float g_xt2[(size_t)NTOT * 96];    // layer2 per-relation transform
__device__ float g_agg2[(size_t)NTOT * 16];   // layer2 accumulator / h2
__device__ int   g_cnt[RN];
__device__ float g_inv[RN];
__device__ float g_W1[448 * 128];             // [n][k]
__device__ float g_W2[112 * 64];              // [n][k]

// ---------------------------------------------------------------------------
// Small helper kernels
// ---------------------------------------------------------------------------
__global__ void zero_cnt_kernel() {
    int i = blockIdx.x * blockDim.x + threadIdx.x;
    if (i < RN) g_cnt[i] = 0;
}

__global__ void count_kernel(const int* __restrict__ dst, const int* __restrict__ et) {
    int e = blockIdx.x * blockDim.x + threadIdx.x;
    if (e < NE) atomicAdd(&g_cnt[et[e] * NTOT + dst[e]], 1);
}

__global__ void inv_kernel() {
    int i = blockIdx.x * blockDim.x + threadIdx.x;
    if (i < RN) {
        int c = g_cnt[i];
        g_inv[i] = 1.0f / (float)(c > 1 ? c : 1);
    }
}

__global__ void build_w1(const float* __restrict__ comp1, const float* __restrict__ bases1,
                         const float* __restrict__ root1) {
    int idx = blockIdx.x * blockDim.x + threadIdx.x;
    if (idx >= 448 * 128) return;
    int n = idx >> 7, k = idx & 127;
    float v;
    if (n < 384) {
        int r = n >> 6, o = n & 63;
        v = 0.0f;
        #pragma unroll
        for (int b = 0; b < 30; b++)
            v += comp1[r * 30 + b] * bases1[((size_t)b * 128 + k) * 64 + o];
    } else {
        v = root1[k * 64 + (n - 384)];
    }
    g_W1[idx] = v;
}

__global__ void build_w2(const float* __restrict__ comp2, const float* __restrict__ bases2,
                         const float* __restrict__ root2) {
    int idx = blockIdx.x * blockDim.x + threadIdx.x;
    if (idx >= 112 * 64) return;
    int n = idx >> 6, k = idx & 63;
    float v;
    if (n < 96) {
        int r = n >> 4, o = n & 15;
        v = 0.0f;
        #pragma unroll
        for (int b = 0; b < 30; b++)
            v += comp2[r * 30 + b] * bases2[((size_t)b * 64 + k) * 16 + o];
    } else {
        v = root2[k * 16 + (n - 96)];
    }
    g_W2[idx] = v;
}

// ---------------------------------------------------------------------------
// TF32 tensor-core GEMM: C[m,n] = sum_k A[m,k]*Bw[n,k] (+bias), split output.
//   cols [0,n1)  -> C1 (+b1),  cols [n1,N) -> C2 (+b2)
// BM=BN=128, BK=32, 256 threads (8 warps, 2x4 m-n warp grid, 64x32 per warp).
// mma.sync.aligned.m16n8k8.row.col.f32.tf32.tf32.f32
// ---------------------------------------------------------------------------
#define BM 128
#define BN 128
#define BK 32

__device__ __forceinline__ unsigned f2tf(float x) {
    unsigned u;
    asm("cvt.rna.tf32.f32 %0, %1;" : "=r"(u) : "f"(x));
    return u;
}

__device__ __forceinline__ void mma_tf32(float* c, const unsigned* a, const unsigned* b) {
    asm volatile(
        "mma.sync.aligned.m16n8k8.row.col.f32.tf32.tf32.f32 "
        "{%0,%1,%2,%3}, {%4,%5,%6,%7}, {%8,%9}, {%0,%1,%2,%3};"
        : "+f"(c[0]), "+f"(c[1]), "+f"(c[2]), "+f"(c[3])
        : "r"(a[0]), "r"(a[1]), "r"(a[2]), "r"(a[3]), "r"(b[0]), "r"(b[1]));
}

__global__ __launch_bounds__(256)
void gemm_tf32(const float* __restrict__ A, const float* __restrict__ Bw,
               int M, int N, int K,
               float* __restrict__ C1, int n1, const float* __restrict__ b1,
               float* __restrict__ C2, const float* __restrict__ b2) {
    __shared__ unsigned As[BM][36];
    __shared__ unsigned Bs[BN][36];

    const int bm = blockIdx.y * BM;
    const int bn = blockIdx.x * BN;
    const int tid = threadIdx.x;
    const int wid = tid >> 5;
    const int lane = tid & 31;
    const int wm = wid & 1;          // 0..1  -> 64 rows each
    const int wn = wid >> 1;         // 0..3  -> 32 cols each
    const int g = lane >> 2;         // 0..7
    const int t = lane & 3;          // 0..3

    float c[4][4][4];
    #pragma unroll
    for (int i = 0; i < 4; i++)
        #pragma unroll
        for (int j = 0; j < 4; j++)
            #pragma unroll
            for (int q = 0; q < 4; q++) c[i][j][q] = 0.0f;

    for (int k0 = 0; k0 < K; k0 += BK) {
        // load A tile: 128 rows x 32 cols, 4 float4 per thread
        #pragma unroll
        for (int i = 0; i < 4; i++) {
            int lin = tid + i * 256;
            int row = lin >> 3;
            int c4 = (lin & 7) * 4;
            float4 v = make_float4(0.f, 0.f, 0.f, 0.f);
            if (bm + row < M)
                v = *(const float4*)(A + (size_t)(bm + row) * K + k0 + c4);
            As[row][c4 + 0] = f2tf(v.x); As[row][c4 + 1] = f2tf(v.y);
            As[row][c4 + 2] = f2tf(v.z); As[row][c4 + 3] = f2tf(v.w);
        }
        // load B tile
        #pragma unroll
        for (int i = 0; i < 4; i++) {
            int lin = tid + i * 256;
            int row = lin >> 3;
            int c4 = (lin & 7) * 4;
            float4 v = make_float4(0.f, 0.f, 0.f, 0.f);
            if (bn + row < N)
                v = *(const float4*)(Bw + (size_t)(bn + row) * K + k0 + c4);
            Bs[row][c4 + 0] = f2tf(v.x); Bs[row][c4 + 1] = f2tf(v.y);
            Bs[row][c4 + 2] = f2tf(v.z); Bs[row][c4 + 3] = f2tf(v.w);
        }
        __syncthreads();

        #pragma unroll
        for (int kk = 0; kk < BK; kk += 8) {
            unsigned a[4][4], b[4][2];
            #pragma unroll
            for (int mt = 0; mt < 4; mt++) {
                int r = wm * 64 + mt * 16 + g;
                a[mt][0] = As[r][kk + t];
                a[mt][1] = As[r + 8][kk + t];
                a[mt][2] = As[r][kk + t + 4];
                a[mt][3] = As[r + 8][kk + t + 4];
            }
            #pragma unroll
            for (int nt = 0; nt < 4; nt++) {
                int cn = wn * 32 + nt * 8 + g;
                b[nt][0] = Bs[cn][kk + t];
                b[nt][1] = Bs[cn][kk + t + 4];
            }
            #pragma unroll
            for (int mt = 0; mt < 4; mt++)
                #pragma unroll
                for (int nt = 0; nt < 4; nt++)
                    mma_tf32(c[mt][nt], a[mt], b[nt]);
        }
        __syncthreads();
    }

    // epilogue: c0=C[g][2t], c1=C[g][2t+1], c2=C[g+8][2t], c3=C[g+8][2t+1]
    const int n2w = N - n1;
    #pragma unroll
    for (int mt = 0; mt < 4; mt++) {
        #pragma unroll
        for (int nt = 0; nt < 4; nt++) {
            int col = bn + wn * 32 + nt * 8 + 2 * t;
            if (col >= N) continue;
            #pragma unroll
            for (int half = 0; half < 2; half++) {
                int row = bm + wm * 64 + mt * 16 + g + half * 8;
                if (row >= M) continue;
                float v0 = c[mt][nt][half * 2 + 0];
                float v1 = c[mt][nt][half * 2 + 1];
                if (col < n1) {
                    if (b1) { v0 += b1[col]; v1 += b1[col + 1]; }
                    *(float2*)(C1 + (size_t)row * n1 + col) = make_float2(v0, v1);
                } else {
                    int cc = col - n1;
                    if (b2) { v0 += b2[cc]; v1 += b2[cc + 1]; }
                    *(float2*)(C2 + (size_t)row * n2w + cc) = make_float2(v0, v1);
                }
            }
        }
    }
}

// ---------------------------------------------------------------------------
// Edge scatter kernels: agg[dst] += inv[type,dst] * xt[src, type*dout .. ]
// ---------------------------------------------------------------------------
__device__ __forceinline__ void red_add_v4(float* addr, float4 v) {
    asm volatile("red.global.add.v4.f32 [%0], {%1, %2, %3, %4};"
                 :: "l"(addr), "f"(v.x), "f"(v.y), "f"(v.z), "f"(v.w)
                 : "memory");
}

__global__ __launch_bounds__(256)
void edge_scatter_64(const int* __restrict__ ei, const int* __restrict__ et) {
    int tglob = blockIdx.x * blockDim.x + threadIdx.x;
    int e = tglob >> 4;
    if (e >= NE) return;
    int lane = tglob & 15;
    int s = ei[e];
    int d = ei[NE + e];
    int r = et[e];
    float w = g_inv[r * NTOT + d];
    float4 v = *(const float4*)(g_xt1 + (size_t)s * 384 + r * 64 + lane * 4);
    red_add_v4(g_agg1 + (size_t)d * 64 + lane * 4,
               make_float4(v.x * w, v.y * w, v.z * w, v.w * w));
}

__global__ __launch_bounds__(256)
void edge_scatter_16(const int* __restrict__ ei, const int* __restrict__ et) {
    int tglob = blockIdx.x * blockDim.x + threadIdx.x;
    int e = tglob >> 2;
    if (e >= NE) return;
    int lane = tglob & 3;
    int s = ei[e];
    int d = ei[NE + e];
    int r = et[e];
    float w = g_inv[r * NTOT + d];
    float4 v = *(const float4*)(g_xt2 + (size_t)s * 96 + r * 16 + lane * 4);
    red_add_v4(g_agg2 + (size_t)d * 16 + lane * 4,
               make_float4(v.x * w, v.y * w, v.z * w, v.w * w));
}

// ---------------------------------------------------------------------------
// Softmax over the first N0 rows (16 cols each)
// ---------------------------------------------------------------------------
__global__ void softmax_kernel(float* __restrict__ out) {
    int row = blockIdx.x * blockDim.x + threadIdx.x;
    if (row >= N0) return;
    const float* p = g_agg2 + (size_t)row * 16;
    float v[16];
    #pragma unroll
    for (int i = 0; i < 4; i++) {
        float4 q = *(const float4*)(p + i * 4);
        v[i * 4 + 0] = q.x; v[i * 4 + 1] = q.y; v[i * 4 + 2] = q.z; v[i * 4 + 3] = q.w;
    }
    float mx = v[0];
    #pragma unroll
    for (int i = 1; i < 16; i++) mx = fmaxf(mx, v[i]);
    float s = 0.0f;
    #pragma unroll
    for (int i = 0; i < 16; i++) { v[i] = expf(v[i] - mx); s += v[i]; }
    float inv = 1.0f / s;
    float* o = out + (size_t)row * 16;
    #pragma unroll
    for (int i = 0; i < 4; i++) {
        float4 q = make_float4(v[i * 4 + 0] * inv, v[i * 4 + 1] * inv,
                               v[i * 4 + 2] * inv, v[i * 4 + 3] * inv);
        *(float4*)(o + i * 4) = q;
    }
}

// ---------------------------------------------------------------------------
// Launcher
// ---------------------------------------------------------------------------
extern "C" void kernel_launch(void* const* d_in, const int* in_sizes, int n_in,
                              void* d_out, int out_size) {
    (void)in_sizes; (void)n_in; (void)out_size;
    const float* x0     = (const float*)d_in[0];
    const float* x1     = (const float*)d_in[1];
    const float* x2     = (const float*)d_in[2];
    const float* lin_w0 = (const float*)d_in[3];
    const float* lin_b0 = (const float*)d_in[4];
    const float* lin_w1 = (const float*)d_in[5];
    const float* lin_b1 = (const float*)d_in[6];
    const float* lin_w2 = (const float*)d_in[7];
    const float* lin_b2 = (const float*)d_in[8];
    const float* bases1 = (const float*)d_in[9];
    const float* comp1  = (const float*)d_in[10];
    const float* root1  = (const float*)d_in[11];
    const float* bias1  = (const float*)d_in[12];
    const float* bases2 = (const float*)d_in[13];
    const float* comp2  = (const float*)d_in[14];
    const float* root2  = (const float*)d_in[15];
    const float* bias2  = (const float*)d_in[16];
    const int*   eidx   = (const int*)d_in[17];
    const int*   etyp   = (const int*)d_in[18];
    float* out = (float*)d_out;

    float *xb, *xt1, *agg1, *xt2, *agg2, *W1, *W2;
    cudaGetSymbolAddress((void**)&xb,   g_x);
    cudaGetSymbolAddress((void**)&xt1,  g_xt1);
    cudaGetSymbolAddress((void**)&agg1, g_agg1);
    cudaGetSymbolAddress((void**)&xt2,  g_xt2);
    cudaGetSymbolAddress((void**)&agg2, g_agg2);
    cudaGetSymbolAddress((void**)&W1,   g_W1);
    cudaGetSymbolAddress((void**)&W2,   g_W2);

    // counts (shared by both layers)
    zero_cnt_kernel<<<(RN + 255) / 256, 256>>>();
    count_kernel<<<(NE + 255) / 256, 256>>>(eidx + NE, etyp);
    inv_kernel<<<(RN + 255) / 256, 256>>>();

    // typed input projections -> g_x
    gemm_tf32<<<dim3(1, (N0 + BM - 1) / BM), 256>>>(
        x0, lin_w0, N0, 128, 256, xb, 128, lin_b0, nullptr, nullptr);
    gemm_tf32<<<dim3(1, (N1 + BM - 1) / BM), 256>>>(
        x1, lin_w1, N1, 128, 512, xb + (size_t)N0 * 128, 128, lin_b1, nullptr, nullptr);
    gemm_tf32<<<dim3(1, (N2 + BM - 1) / BM), 256>>>(
        x2, lin_w2, N2, 128, 128, xb + (size_t)(N0 + N1) * 128, 128, lin_b2, nullptr, nullptr);

    // layer 1: xt1 (relation cols) + agg1 init (root+bias cols)
    build_w1<<<(448 * 128 + 255) / 256, 256>>>(comp1, bases1, root1);
    gemm_tf32<<<dim3(4, (NTOT + BM - 1) / BM), 256>>>(
        xb, W1, NTOT, 448, 128, xt1, 384, nullptr, agg1, bias1);
    edge_scatter_64<<<(NE * 16) / 256, 256>>>(eidx, etyp);

    // layer 2: xt2 + agg2 init
    build_w2<<<(112 * 64 + 255) / 256, 256>>>(comp2, bases2, root2);
    gemm_tf32<<<dim3(1, (NTOT + BM - 1) / BM), 256>>>(
        agg1, W2, NTOT, 112, 64, xt2, 96, nullptr, agg2, bias2);
    edge_scatter_16<<<(NE * 4) / 256, 256>>>(eidx, etyp);

    // softmax over author rows
    softmax_kernel<<<(N0 + 255) / 256, 256>>>(out);
}